// round 4
// baseline (speedup 1.0000x reference)
#include <cuda_runtime.h>

#define Bq 8192
#define Nn 524288
#define Hh 256
#define KDd 128
#define VDd 128
#define SCALE 0.08838834764831845f  /* 1/sqrt(128) */

// ---------------- scratch (device globals; no allocation allowed) -----------
__device__ __align__(16) float g_rs[Bq * Hh];     // per-graph folded key-proj vector (scaled)
__device__ __align__(16) float g_u[Bq * Hh];      // per-graph sum of e_n * value_n
__device__ __align__(16) float g_denom[Bq];       // per-graph sum of e_n
__device__ __align__(16) float g_AT[KDd * Hh];    // [128][256]: AT[i][j] = scale * sum_t Wk[t][j]*Wq[t][i]
__device__ __align__(16) float g_a0[Hh];          // scale * Wk^T bq
__device__ __align__(16) float g_Mt[Hh * VDd];    // [256][128]: Mt[j][p] = sum_o Wo[p][o]*Wv[o][j]
__device__ __align__(16) float g_d[VDd];          // Wo bv + bo

// ---------------- prep: AT, a0 ------------------------------------------------
// cs_b (scale*bk.q~_b) is constant per segment -> cancels in the softmax ratio
// (same shift-invariance that lets us skip segment_max). Not computed at all.
__global__ void prep_AT(const float* __restrict__ Wq, const float* __restrict__ bq,
                        const float* __restrict__ Wk, const float* __restrict__ bk) {
    __shared__ float col[KDd];
    int bi = blockIdx.x;
    int t = threadIdx.x;  // 256 threads
    if (t < KDd) col[t] = (bi < KDd) ? Wq[t * KDd + bi] : bq[t];
    __syncthreads();
    float s = 0.0f;
    #pragma unroll 8
    for (int r = 0; r < KDd; ++r) s += Wk[r * Hh + t] * col[r];
    if (bi < KDd) g_AT[bi * Hh + t] = s * SCALE;
    else          g_a0[t] = s * SCALE;
}

// ---------------- prep: Mt = (Wo@Wv)^T, d = Wo bv + bo -----------------------
__global__ void prep_Mt(const float* __restrict__ Wv, const float* __restrict__ bv,
                        const float* __restrict__ Wo, const float* __restrict__ bo) {
    __shared__ float sv[VDd];
    int j = blockIdx.x;      // 0..255 -> Mt row j; 256 -> d
    int p = threadIdx.x;     // 128 threads
    sv[p] = (j < Hh) ? Wv[p * Hh + j] : bv[p];
    __syncthreads();
    float acc = 0.0f;
    const float4* wrow = (const float4*)(Wo + p * VDd);
    #pragma unroll 8
    for (int o4 = 0; o4 < VDd / 4; ++o4) {
        float4 w = wrow[o4];
        int o = o4 * 4;
        acc += w.x * sv[o] + w.y * sv[o + 1] + w.z * sv[o + 2] + w.w * sv[o + 3];
    }
    if (j < Hh) g_Mt[j * VDd + p] = acc;
    else        g_d[p] = acc + bo[p];
}

// ---------------- 64x128-tile fp32 GEMM, 4x8 microtile ------------------------
// MODE 0: g_rs = query @ g_AT + g_a0          (K=128, NOUT=256) + zero-init g_u
// MODE 1: out  = (g_u/denom) @ g_Mt + g_d     (K=256, NOUT=128)
template <int MODE>
__global__ __launch_bounds__(256) void gemm64(const float* __restrict__ Xext,
                                              float* __restrict__ Cext,
                                              const float* __restrict__ boext) {
    constexpr int K = (MODE == 0) ? KDd : Hh;
    constexpr int NOUT = (MODE == 0) ? Hh : VDd;
    const float* X = (MODE == 0) ? Xext : g_u;
    const float* W = (MODE == 0) ? g_AT : g_Mt;
    const float* bias = (MODE == 0) ? g_a0 : g_d;

    const int tid = threadIdx.x;

    if (MODE == 0) {
        // fold the g_u/g_denom zero-init into this kernel (256 blocks cover all)
        int bid = blockIdx.y * gridDim.x + blockIdx.x;  // 0..255
        float4 z = make_float4(0.f, 0.f, 0.f, 0.f);
        float4* u4 = (float4*)g_u;
        #pragma unroll
        for (int r = 0; r < 8; ++r) u4[(size_t)bid * 2048 + r * 256 + tid] = z;
        if (tid < 32) g_denom[bid * 32 + tid] = 0.0f;
    }

    __shared__ float Xs[16][68];     // transposed A tile
    __shared__ float Ws[16][128];    // B tile rows

    const int m0 = blockIdx.y * 64;
    const int n0 = blockIdx.x * 128;
    const int tm = tid >> 4;            // 0..15 -> 4 rows each
    const int tn = tid & 15;            // 0..15 -> 8 cols each
    const int ar = tid >> 2;            // 0..63
    const int ac = (tid & 3) << 2;      // 0,4,8,12
    const int br = tid >> 4;            // 0..15
    const int bc = (tid & 15) << 3;     // 0..120

    float acc[4][8] = {};

    for (int kc = 0; kc < K; kc += 16) {
        float4 xv = *(const float4*)(X + (size_t)(m0 + ar) * K + kc + ac);
        Xs[ac + 0][ar] = xv.x;
        Xs[ac + 1][ar] = xv.y;
        Xs[ac + 2][ar] = xv.z;
        Xs[ac + 3][ar] = xv.w;
        const float* wsrc = W + (size_t)(kc + br) * NOUT + n0 + bc;
        *(float4*)&Ws[br][bc + 0] = *(const float4*)(wsrc + 0);
        *(float4*)&Ws[br][bc + 4] = *(const float4*)(wsrc + 4);
        __syncthreads();
        #pragma unroll
        for (int kk = 0; kk < 16; ++kk) {
            float4 av = *(const float4*)&Xs[kk][tm << 2];
            float4 b0 = *(const float4*)&Ws[kk][tn << 3];
            float4 b1 = *(const float4*)&Ws[kk][(tn << 3) + 4];
            float a[4] = {av.x, av.y, av.z, av.w};
            #pragma unroll
            for (int i = 0; i < 4; ++i) {
                acc[i][0] += a[i] * b0.x; acc[i][1] += a[i] * b0.y;
                acc[i][2] += a[i] * b0.z; acc[i][3] += a[i] * b0.w;
                acc[i][4] += a[i] * b1.x; acc[i][5] += a[i] * b1.y;
                acc[i][6] += a[i] * b1.z; acc[i][7] += a[i] * b1.w;
            }
        }
        __syncthreads();
    }

    const int col = n0 + (tn << 3);
    float bx[8];
    #pragma unroll
    for (int j = 0; j < 8; ++j) bx[j] = bias[col + j];

    #pragma unroll
    for (int i = 0; i < 4; ++i) {
        int m = m0 + (tm << 2) + i;
        float o[8];
        if (MODE == 0) {
            #pragma unroll
            for (int j = 0; j < 8; ++j) o[j] = acc[i][j] + bx[j];
            *(float4*)(g_rs + (size_t)m * NOUT + col) = make_float4(o[0], o[1], o[2], o[3]);
            *(float4*)(g_rs + (size_t)m * NOUT + col + 4) = make_float4(o[4], o[5], o[6], o[7]);
        } else {
            float den = g_denom[m];
            if (den > 0.0f) {
                float inv = 1.0f / den;
                #pragma unroll
                for (int j = 0; j < 8; ++j) o[j] = acc[i][j] * inv + bx[j];
            } else {
                #pragma unroll
                for (int j = 0; j < 8; ++j) o[j] = boext[col + j];
            }
            *(float4*)(Cext + (size_t)m * NOUT + col) = make_float4(o[0], o[1], o[2], o[3]);
            *(float4*)(Cext + (size_t)m * NOUT + col + 4) = make_float4(o[4], o[5], o[6], o[7]);
        }
    }
}

// ---------------- fused main pass ---------------------------------------------
__device__ __forceinline__ void seg_flush(int b, int lane, float4 a0, float4 a1, float dacc) {
    float* up = g_u + (size_t)b * Hh;
    atomicAdd(up + lane * 4 + 0, a0.x);
    atomicAdd(up + lane * 4 + 1, a0.y);
    atomicAdd(up + lane * 4 + 2, a0.z);
    atomicAdd(up + lane * 4 + 3, a0.w);
    atomicAdd(up + 128 + lane * 4 + 0, a1.x);
    atomicAdd(up + 128 + lane * 4 + 1, a1.y);
    atomicAdd(up + 128 + lane * 4 + 2, a1.z);
    atomicAdd(up + 128 + lane * 4 + 3, a1.w);
    if (lane == 0) atomicAdd(&g_denom[b], dacc);
}

__device__ __forceinline__ float dot8(float4 k0, float4 k1, float4 r0, float4 r1) {
    return k0.x * r0.x + k0.y * r0.y + k0.z * r0.z + k0.w * r0.w
         + k1.x * r1.x + k1.y * r1.y + k1.z * r1.z + k1.w * r1.w;
}

// 1 warp per 64-node chunk; unroll 2 nodes/iter; double-buffer BOTH key and
// value rows one pair ahead so every consumed operand is a full iteration old.
__global__ __launch_bounds__(256, 2) void fused_attn(const float* __restrict__ key,
                                                     const float* __restrict__ value,
                                                     const int* __restrict__ batch) {
    const int wid = (blockIdx.x * blockDim.x + threadIdx.x) >> 5;
    const int lane = threadIdx.x & 31;
    const int n0 = wid * 64;
    if (n0 >= Nn) return;

    const float4* __restrict__ key4 = (const float4*)key;
    const float4* __restrict__ val4 = (const float4*)value;
    const float4* __restrict__ rs4 = (const float4*)g_rs;

    int cur = batch[n0] & (Bq - 1);
    float4 r0 = rs4[cur * 64 + lane];
    float4 r1 = rs4[cur * 64 + 32 + lane];

    float4 a0 = make_float4(0.f, 0.f, 0.f, 0.f);
    float4 a1 = make_float4(0.f, 0.f, 0.f, 0.f);
    float dacc = 0.0f;

    // prime both k and v prefetch for first pair
    float4 ka0 = key4[(size_t)n0 * 64 + lane];
    float4 ka1 = key4[(size_t)n0 * 64 + 32 + lane];
    float4 kb0 = key4[(size_t)(n0 + 1) * 64 + lane];
    float4 kb1 = key4[(size_t)(n0 + 1) * 64 + 32 + lane];
    float4 va0 = val4[(size_t)n0 * 64 + lane];
    float4 va1 = val4[(size_t)n0 * 64 + 32 + lane];
    float4 vb0 = val4[(size_t)(n0 + 1) * 64 + lane];
    float4 vb1 = val4[(size_t)(n0 + 1) * 64 + 32 + lane];

    const int n_end = n0 + 64;
    for (int n = n0; n < n_end; n += 2) {
        int2 bb = *(const int2*)(batch + n);
        int b0 = bb.x & (Bq - 1);
        int b1 = bb.y & (Bq - 1);

        // prefetch next pair (clamped; every chunk is full since Nn % 64 == 0)
        int np = n + 2 < Nn ? n + 2 : Nn - 2;
        float4 kc0 = key4[(size_t)np * 64 + lane];
        float4 kc1 = key4[(size_t)np * 64 + 32 + lane];
        float4 kd0 = key4[(size_t)(np + 1) * 64 + lane];
        float4 kd1 = key4[(size_t)(np + 1) * 64 + 32 + lane];
        float4 vc0 = val4[(size_t)np * 64 + lane];
        float4 vc1 = val4[(size_t)np * 64 + 32 + lane];
        float4 vd0 = val4[(size_t)(np + 1) * 64 + lane];
        float4 vd1 = val4[(size_t)(np + 1) * 64 + 32 + lane];

        if (b0 == cur && b1 == cur) {
            // fast path (~97% of pairs)
            float pA = dot8(ka0, ka1, r0, r1);
            float pB = dot8(kb0, kb1, r0, r1);
            #pragma unroll
            for (int off = 16; off; off >>= 1) {
                pA += __shfl_xor_sync(0xffffffffu, pA, off);
                pB += __shfl_xor_sync(0xffffffffu, pB, off);
            }
            float eA = __expf(pA);
            float eB = __expf(pB);
            a0.x += eA * va0.x + eB * vb0.x; a0.y += eA * va0.y + eB * vb0.y;
            a0.z += eA * va0.z + eB * vb0.z; a0.w += eA * va0.w + eB * vb0.w;
            a1.x += eA * va1.x + eB * vb1.x; a1.y += eA * va1.y + eB * vb1.y;
            a1.z += eA * va1.z + eB * vb1.z; a1.w += eA * va1.w + eB * vb1.w;
            dacc += eA + eB;
        } else {
            // boundary path
            if (b0 != cur) {
                seg_flush(cur, lane, a0, a1, dacc);
                a0 = make_float4(0.f, 0.f, 0.f, 0.f);
                a1 = make_float4(0.f, 0.f, 0.f, 0.f);
                dacc = 0.0f;
                cur = b0;
                r0 = rs4[cur * 64 + lane];
                r1 = rs4[cur * 64 + 32 + lane];
            }
            float pA = dot8(ka0, ka1, r0, r1);
            #pragma unroll
            for (int off = 16; off; off >>= 1) pA += __shfl_xor_sync(0xffffffffu, pA, off);
            float eA = __expf(pA);
            a0.x += eA * va0.x; a0.y += eA * va0.y; a0.z += eA * va0.z; a0.w += eA * va0.w;
            a1.x += eA * va1.x; a1.y += eA * va1.y; a1.z += eA * va1.z; a1.w += eA * va1.w;
            dacc += eA;

            if (b1 != cur) {
                seg_flush(cur, lane, a0, a1, dacc);
                a0 = make_float4(0.f, 0.f, 0.f, 0.f);
                a1 = make_float4(0.f, 0.f, 0.f, 0.f);
                dacc = 0.0f;
                cur = b1;
                r0 = rs4[cur * 64 + lane];
                r1 = rs4[cur * 64 + 32 + lane];
            }
            float pB = dot8(kb0, kb1, r0, r1);
            #pragma unroll
            for (int off = 16; off; off >>= 1) pB += __shfl_xor_sync(0xffffffffu, pB, off);
            float eB = __expf(pB);
            a0.x += eB * vb0.x; a0.y += eB * vb0.y; a0.z += eB * vb0.z; a0.w += eB * vb0.w;
            a1.x += eB * vb1.x; a1.y += eB * vb1.y; a1.z += eB * vb1.z; a1.w += eB * vb1.w;
            dacc += eB;
        }

        // rotate prefetch buffers
        ka0 = kc0; ka1 = kc1; kb0 = kd0; kb1 = kd1;
        va0 = vc0; va1 = vc1; vb0 = vd0; vb1 = vd1;
    }
    seg_flush(cur, lane, a0, a1, dacc);
}

// ---------------- launch ------------------------------------------------------
extern "C" void kernel_launch(void* const* d_in, const int* in_sizes, int n_in,
                              void* d_out, int out_size) {
    const float* query = (const float*)d_in[0];
    const float* key = (const float*)d_in[1];
    const float* value = (const float*)d_in[2];
    const int* batch = (const int*)d_in[3];
    const float* Wq = (const float*)d_in[4];
    const float* bq = (const float*)d_in[5];
    const float* Wk = (const float*)d_in[6];
    const float* bk = (const float*)d_in[7];
    const float* Wv = (const float*)d_in[8];
    const float* bv = (const float*)d_in[9];
    const float* Wo = (const float*)d_in[10];
    const float* bo = (const float*)d_in[11];
    float* out = (float*)d_out;

    prep_AT<<<129, 256>>>(Wq, bq, Wk, bk);
    prep_Mt<<<257, 128>>>(Wv, bv, Wo, bo);
    gemm64<0><<<dim3(Hh / 128, Bq / 64), 256>>>(query, nullptr, nullptr);   // 2 x 128 = 256 blocks (also zeroes g_u/g_denom)
    fused_attn<<<Nn / 64 / 8, 256>>>(key, value, batch);
    gemm64<1><<<dim3(VDd / 128, Bq / 64), 256>>>(nullptr, out, bo);         // 1 x 128 = 128 blocks
}

// round 5
// speedup vs baseline: 1.0522x; 1.0522x over previous
#include <cuda_runtime.h>

#define Bq 8192
#define Nn 524288
#define Hh 256
#define KDd 128
#define VDd 128
#define SCALE 0.08838834764831845f  /* 1/sqrt(128) */

// ---------------- scratch (device globals; no allocation allowed) -----------
__device__ __align__(16) float g_rs[Bq * Hh];     // per-graph folded key-proj vector (scaled)
__device__ __align__(16) float g_u[Bq * Hh];      // per-graph sum of e_n * value_n
__device__ __align__(16) float g_denom[Bq];       // per-graph sum of e_n
__device__ __align__(16) float g_AT[KDd * Hh];    // [128][256]
__device__ __align__(16) float g_a0[Hh];          // scale * Wk^T bq
__device__ __align__(16) float g_Mt[Hh * VDd];    // [256][128]
__device__ __align__(16) float g_d[VDd];          // Wo bv + bo

// ---------------- prep: AT, a0 ------------------------------------------------
// cs_b (scale*bk.q~_b) is constant per segment -> cancels in the softmax ratio.
__global__ void prep_AT(const float* __restrict__ Wq, const float* __restrict__ bq,
                        const float* __restrict__ Wk, const float* __restrict__ bk) {
    __shared__ float col[KDd];
    int bi = blockIdx.x;
    int t = threadIdx.x;  // 256 threads
    if (t < KDd) col[t] = (bi < KDd) ? Wq[t * KDd + bi] : bq[t];
    __syncthreads();
    float s = 0.0f;
    #pragma unroll 8
    for (int r = 0; r < KDd; ++r) s += Wk[r * Hh + t] * col[r];
    if (bi < KDd) g_AT[bi * Hh + t] = s * SCALE;
    else          g_a0[t] = s * SCALE;
}

// ---------------- prep: Mt = (Wo@Wv)^T, d = Wo bv + bo -----------------------
__global__ void prep_Mt(const float* __restrict__ Wv, const float* __restrict__ bv,
                        const float* __restrict__ Wo, const float* __restrict__ bo) {
    __shared__ float sv[VDd];
    int j = blockIdx.x;      // 0..255 -> Mt row j; 256 -> d
    int p = threadIdx.x;     // 128 threads
    sv[p] = (j < Hh) ? Wv[p * Hh + j] : bv[p];
    __syncthreads();
    float acc = 0.0f;
    const float4* wrow = (const float4*)(Wo + p * VDd);
    #pragma unroll 8
    for (int o4 = 0; o4 < VDd / 4; ++o4) {
        float4 w = wrow[o4];
        int o = o4 * 4;
        acc += w.x * sv[o] + w.y * sv[o + 1] + w.z * sv[o + 2] + w.w * sv[o + 3];
    }
    if (j < Hh) g_Mt[j * VDd + p] = acc;
    else        g_d[p] = acc + bo[p];
}

// ---------------- 64x64-tile fp32 GEMM (REVERTED to measured-good version) ---
// MODE 0: g_rs = query @ g_AT + g_a0   (K=128, NOUT=256), 512 blocks, + zero g_u
// MODE 1: out  = (g_u/denom) @ g_Mt + g_d   (K=256, NOUT=128), 256 blocks
template <int MODE>
__global__ __launch_bounds__(256) void gemm64(const float* __restrict__ Xext,
                                              float* __restrict__ Cext,
                                              const float* __restrict__ boext) {
    constexpr int K = (MODE == 0) ? KDd : Hh;
    constexpr int NOUT = (MODE == 0) ? Hh : VDd;
    const float* X = (MODE == 0) ? Xext : g_u;
    const float* W = (MODE == 0) ? g_AT : g_Mt;
    const float* bias = (MODE == 0) ? g_a0 : g_d;

    const int tid = threadIdx.x;

    if (MODE == 0) {
        // fold g_u/g_denom zero-init into this kernel (512 blocks cover all)
        int bid = blockIdx.y * gridDim.x + blockIdx.x;  // 0..511
        float4 z = make_float4(0.f, 0.f, 0.f, 0.f);
        float4* u4 = (float4*)g_u;
        #pragma unroll
        for (int r = 0; r < 4; ++r) u4[(size_t)bid * 1024 + r * 256 + tid] = z;
        if (tid < 16) g_denom[bid * 16 + tid] = 0.0f;
    }

    __shared__ float Xs[16][72];
    __shared__ float Ws[16][64];

    const int m0 = blockIdx.y * 64;
    const int n0 = blockIdx.x * 64;
    const int tn = tid & 15;
    const int tm = tid >> 4;
    const int lxr = tid >> 2;
    const int lxc = (tid & 3) << 2;
    const int lwr = tid >> 4;
    const int lwc = (tid & 15) << 2;

    float acc[4][4] = {};

    for (int kc = 0; kc < K; kc += 16) {
        float4 xv = *(const float4*)(X + (size_t)(m0 + lxr) * K + kc + lxc);
        Xs[lxc + 0][lxr] = xv.x;
        Xs[lxc + 1][lxr] = xv.y;
        Xs[lxc + 2][lxr] = xv.z;
        Xs[lxc + 3][lxr] = xv.w;
        *(float4*)&Ws[lwr][lwc] = *(const float4*)(W + (size_t)(kc + lwr) * NOUT + n0 + lwc);
        __syncthreads();
        #pragma unroll
        for (int kk = 0; kk < 16; ++kk) {
            float4 av = *(const float4*)&Xs[kk][tm << 2];
            float4 bv4 = *(const float4*)&Ws[kk][tn << 2];
            acc[0][0] += av.x * bv4.x; acc[0][1] += av.x * bv4.y; acc[0][2] += av.x * bv4.z; acc[0][3] += av.x * bv4.w;
            acc[1][0] += av.y * bv4.x; acc[1][1] += av.y * bv4.y; acc[1][2] += av.y * bv4.z; acc[1][3] += av.y * bv4.w;
            acc[2][0] += av.z * bv4.x; acc[2][1] += av.z * bv4.y; acc[2][2] += av.z * bv4.z; acc[2][3] += av.z * bv4.w;
            acc[3][0] += av.w * bv4.x; acc[3][1] += av.w * bv4.y; acc[3][2] += av.w * bv4.z; acc[3][3] += av.w * bv4.w;
        }
        __syncthreads();
    }

    const int col = n0 + (tn << 2);
    #pragma unroll
    for (int i = 0; i < 4; ++i) {
        int m = m0 + (tm << 2) + i;
        float4 o;
        if (MODE == 0) {
            o.x = acc[i][0] + bias[col + 0];
            o.y = acc[i][1] + bias[col + 1];
            o.z = acc[i][2] + bias[col + 2];
            o.w = acc[i][3] + bias[col + 3];
            *(float4*)(g_rs + (size_t)m * NOUT + col) = o;
        } else {
            float den = g_denom[m];
            if (den > 0.0f) {
                float inv = 1.0f / den;
                o.x = acc[i][0] * inv + bias[col + 0];
                o.y = acc[i][1] * inv + bias[col + 1];
                o.z = acc[i][2] * inv + bias[col + 2];
                o.w = acc[i][3] * inv + bias[col + 3];
            } else {
                o.x = boext[col + 0];
                o.y = boext[col + 1];
                o.z = boext[col + 2];
                o.w = boext[col + 3];
            }
            *(float4*)(Cext + (size_t)m * NOUT + col) = o;
        }
    }
}

// ---------------- fused main pass ---------------------------------------------
__device__ __forceinline__ void seg_flush(int b, int lane, float4 a0, float4 a1, float dacc) {
    float* up = g_u + (size_t)b * Hh;
    atomicAdd(up + lane * 4 + 0, a0.x);
    atomicAdd(up + lane * 4 + 1, a0.y);
    atomicAdd(up + lane * 4 + 2, a0.z);
    atomicAdd(up + lane * 4 + 3, a0.w);
    atomicAdd(up + 128 + lane * 4 + 0, a1.x);
    atomicAdd(up + 128 + lane * 4 + 1, a1.y);
    atomicAdd(up + 128 + lane * 4 + 2, a1.z);
    atomicAdd(up + 128 + lane * 4 + 3, a1.w);
    if (lane == 0) atomicAdd(&g_denom[b], dacc);
}

__device__ __forceinline__ float dot8(float4 k0, float4 k1, float4 r0, float4 r1) {
    return k0.x * r0.x + k0.y * r0.y + k0.z * r0.z + k0.w * r0.w
         + k1.x * r1.x + k1.y * r1.y + k1.z * r1.z + k1.w * r1.w;
}

// 1 warp per 64-node chunk, 2 nodes/iter. Register diet: the key buffers are
// consumed by the dots at the TOP of the iteration, then immediately
// overwritten with the NEXT pair's rows (in-place prefetch, no extra buffers).
// Peak live ~11 float4 -> ~85 regs -> 3 blocks/SM (24 warps) via (256,3).
__global__ __launch_bounds__(256, 3) void fused_attn(const float* __restrict__ key,
                                                     const float* __restrict__ value,
                                                     const int* __restrict__ batch) {
    const int wid = (blockIdx.x * blockDim.x + threadIdx.x) >> 5;
    const int lane = threadIdx.x & 31;
    const int n0 = wid * 64;
    if (n0 >= Nn) return;

    const float4* __restrict__ key4 = (const float4*)key;
    const float4* __restrict__ val4 = (const float4*)value;
    const float4* __restrict__ rs4 = (const float4*)g_rs;

    int cur = batch[n0] & (Bq - 1);
    float4 r0 = rs4[cur * 64 + lane];
    float4 r1 = rs4[cur * 64 + 32 + lane];

    float4 a0 = make_float4(0.f, 0.f, 0.f, 0.f);
    float4 a1 = make_float4(0.f, 0.f, 0.f, 0.f);
    float dacc = 0.0f;

    // prime key buffers with first pair
    float4 ka0 = key4[(size_t)n0 * 64 + lane];
    float4 ka1 = key4[(size_t)n0 * 64 + 32 + lane];
    float4 kb0 = key4[(size_t)(n0 + 1) * 64 + lane];
    float4 kb1 = key4[(size_t)(n0 + 1) * 64 + 32 + lane];

    const int n_end = n0 + 64;
    for (int n = n0; n < n_end; n += 2) {
        int2 bb = *(const int2*)(batch + n);
        int b0 = bb.x & (Bq - 1);
        int b1 = bb.y & (Bq - 1);
        int np = n + 2 < Nn ? n + 2 : Nn - 2;   // in-bounds prefetch target

        if (b0 == cur && b1 == cur) {
            // fast path: dots consume ka..kb, then reuse those regs for next keys
            float pA = dot8(ka0, ka1, r0, r1);
            float pB = dot8(kb0, kb1, r0, r1);

            ka0 = key4[(size_t)np * 64 + lane];
            ka1 = key4[(size_t)np * 64 + 32 + lane];
            kb0 = key4[(size_t)(np + 1) * 64 + lane];
            kb1 = key4[(size_t)(np + 1) * 64 + 32 + lane];

            float4 va0 = val4[(size_t)n * 64 + lane];
            float4 va1 = val4[(size_t)n * 64 + 32 + lane];
            float4 vb0 = val4[(size_t)(n + 1) * 64 + lane];
            float4 vb1 = val4[(size_t)(n + 1) * 64 + 32 + lane];

            #pragma unroll
            for (int off = 16; off; off >>= 1) {
                pA += __shfl_xor_sync(0xffffffffu, pA, off);
                pB += __shfl_xor_sync(0xffffffffu, pB, off);
            }
            float eA = __expf(pA);
            float eB = __expf(pB);
            a0.x += eA * va0.x + eB * vb0.x; a0.y += eA * va0.y + eB * vb0.y;
            a0.z += eA * va0.z + eB * vb0.z; a0.w += eA * va0.w + eB * vb0.w;
            a1.x += eA * va1.x + eB * vb1.x; a1.y += eA * va1.y + eB * vb1.y;
            a1.z += eA * va1.z + eB * vb1.z; a1.w += eA * va1.w + eB * vb1.w;
            dacc += eA + eB;
        } else {
            // boundary path (~3% of pairs): sequential, reload rs on switch
            float4 va0 = val4[(size_t)n * 64 + lane];
            float4 va1 = val4[(size_t)n * 64 + 32 + lane];
            float4 vb0 = val4[(size_t)(n + 1) * 64 + lane];
            float4 vb1 = val4[(size_t)(n + 1) * 64 + 32 + lane];

            if (b0 != cur) {
                seg_flush(cur, lane, a0, a1, dacc);
                a0 = make_float4(0.f, 0.f, 0.f, 0.f);
                a1 = make_float4(0.f, 0.f, 0.f, 0.f);
                dacc = 0.0f;
                cur = b0;
                r0 = rs4[cur * 64 + lane];
                r1 = rs4[cur * 64 + 32 + lane];
            }
            float pA = dot8(ka0, ka1, r0, r1);
            #pragma unroll
            for (int off = 16; off; off >>= 1) pA += __shfl_xor_sync(0xffffffffu, pA, off);
            float eA = __expf(pA);
            a0.x += eA * va0.x; a0.y += eA * va0.y; a0.z += eA * va0.z; a0.w += eA * va0.w;
            a1.x += eA * va1.x; a1.y += eA * va1.y; a1.z += eA * va1.z; a1.w += eA * va1.w;
            dacc += eA;

            if (b1 != cur) {
                seg_flush(cur, lane, a0, a1, dacc);
                a0 = make_float4(0.f, 0.f, 0.f, 0.f);
                a1 = make_float4(0.f, 0.f, 0.f, 0.f);
                dacc = 0.0f;
                cur = b1;
                r0 = rs4[cur * 64 + lane];
                r1 = rs4[cur * 64 + 32 + lane];
            }
            float pB = dot8(kb0, kb1, r0, r1);
            #pragma unroll
            for (int off = 16; off; off >>= 1) pB += __shfl_xor_sync(0xffffffffu, pB, off);
            float eB = __expf(pB);
            a0.x += eB * vb0.x; a0.y += eB * vb0.y; a0.z += eB * vb0.z; a0.w += eB * vb0.w;
            a1.x += eB * vb1.x; a1.y += eB * vb1.y; a1.z += eB * vb1.z; a1.w += eB * vb1.w;
            dacc += eB;

            // reload key buffers for next pair
            ka0 = key4[(size_t)np * 64 + lane];
            ka1 = key4[(size_t)np * 64 + 32 + lane];
            kb0 = key4[(size_t)(np + 1) * 64 + lane];
            kb1 = key4[(size_t)(np + 1) * 64 + 32 + lane];
        }
    }
    seg_flush(cur, lane, a0, a1, dacc);
}

// ---------------- launch ------------------------------------------------------
extern "C" void kernel_launch(void* const* d_in, const int* in_sizes, int n_in,
                              void* d_out, int out_size) {
    const float* query = (const float*)d_in[0];
    const float* key = (const float*)d_in[1];
    const float* value = (const float*)d_in[2];
    const int* batch = (const int*)d_in[3];
    const float* Wq = (const float*)d_in[4];
    const float* bq = (const float*)d_in[5];
    const float* Wk = (const float*)d_in[6];
    const float* bk = (const float*)d_in[7];
    const float* Wv = (const float*)d_in[8];
    const float* bv = (const float*)d_in[9];
    const float* Wo = (const float*)d_in[10];
    const float* bo = (const float*)d_in[11];
    float* out = (float*)d_out;

    prep_AT<<<129, 256>>>(Wq, bq, Wk, bk);
    prep_Mt<<<257, 128>>>(Wv, bv, Wo, bo);
    gemm64<0><<<dim3(Hh / 64, Bq / 64), 256>>>(query, nullptr, nullptr);  // 512 blocks, zeroes g_u/g_denom
    fused_attn<<<Nn / 64 / 8, 256>>>(key, value, batch);
    gemm64<1><<<dim3(VDd / 64, Bq / 64), 256>>>(nullptr, out, bo);        // 256 blocks
}

// round 6
// speedup vs baseline: 1.0970x; 1.0426x over previous
#include <cuda_runtime.h>
#include <cstdint>

#define Bq 8192
#define Nn 524288
#define Hh 256
#define KDd 128
#define VDd 128
#define SCALE 0.08838834764831845f  /* 1/sqrt(128) */

// ---------------- scratch (device globals; no allocation allowed) -----------
__device__ __align__(16) float g_rs[Bq * Hh];     // per-graph folded key-proj vector (scaled)
__device__ __align__(16) float g_u[Bq * Hh];      // per-graph sum of e_n * value_n
__device__ __align__(16) float g_denom[Bq];       // per-graph sum of e_n
__device__ __align__(16) float g_AT[KDd * Hh];    // [128][256]
__device__ __align__(16) float g_a0[Hh];          // scale * Wk^T bq
__device__ __align__(16) float g_Mt[Hh * VDd];    // [256][128]
__device__ __align__(16) float g_d[VDd];          // Wo bv + bo

// ---------------- merged prep: AT/a0 (blocks 0..128), Mt/d (blocks 129..385) --
// cs_b (scale*bk.q~_b) is constant per segment -> cancels in the softmax ratio.
__global__ void prep_all(const float* __restrict__ Wq, const float* __restrict__ bq,
                         const float* __restrict__ Wk, const float* __restrict__ bk,
                         const float* __restrict__ Wv, const float* __restrict__ bv,
                         const float* __restrict__ Wo, const float* __restrict__ bo) {
    __shared__ float col[Hh];
    int blk = blockIdx.x;
    int t = threadIdx.x;  // 256 threads
    if (blk < KDd + 1) {
        // AT[bi][t] = scale * sum_r Wk[r][t] * Wq[r][bi]   (bi==KDd -> a0 with bq)
        int bi = blk;
        if (t < KDd) col[t] = (bi < KDd) ? Wq[t * KDd + bi] : bq[t];
        __syncthreads();
        float s = 0.0f;
        #pragma unroll 8
        for (int r = 0; r < KDd; ++r) s += Wk[r * Hh + t] * col[r];
        if (bi < KDd) g_AT[bi * Hh + t] = s * SCALE;
        else          g_a0[t] = s * SCALE;
    } else {
        // Mt[j][p] = sum_o Wo[p][o]*Wv[o][j]  (j==Hh -> d with bv, +bo)
        int j = blk - (KDd + 1);   // 0..256
        if (t < VDd) col[t] = (j < Hh) ? Wv[t * Hh + j] : bv[t];
        __syncthreads();
        if (t < VDd) {
            float acc = 0.0f;
            const float4* wrow = (const float4*)(Wo + t * VDd);
            #pragma unroll 8
            for (int o4 = 0; o4 < VDd / 4; ++o4) {
                float4 w = wrow[o4];
                int o = o4 * 4;
                acc += w.x * col[o] + w.y * col[o + 1] + w.z * col[o + 2] + w.w * col[o + 3];
            }
            if (j < Hh) g_Mt[j * VDd + t] = acc;
            else        g_d[t] = acc + bo[t];
        }
    }
}

// ---------------- tf32 helpers -------------------------------------------------
__device__ __forceinline__ uint32_t f2tf32(float x) {
    uint32_t r;
    asm("cvt.rna.tf32.f32 %0, %1;" : "=r"(r) : "f"(x));
    return r;
}

__device__ __forceinline__ void mma_tf32(float* c, const uint32_t* a, uint32_t b0, uint32_t b1) {
    asm volatile(
        "mma.sync.aligned.m16n8k8.row.col.f32.tf32.tf32.f32 "
        "{%0,%1,%2,%3}, {%4,%5,%6,%7}, {%8,%9}, {%0,%1,%2,%3};"
        : "+f"(c[0]), "+f"(c[1]), "+f"(c[2]), "+f"(c[3])
        : "r"(a[0]), "r"(a[1]), "r"(a[2]), "r"(a[3]), "r"(b0), "r"(b1));
}

// ---------------- tensor-core 3xtf32 GEMM -------------------------------------
// Block: 256 threads (8 warps). Block tile M=128, N=64. Warp = 16-row strip x 64 cols.
// MODE 0: g_rs = query @ g_AT + g_a0     (K=128, NOUT=256), grid (4,64) + zero g_u
// MODE 1: out  = (g_u/denom) @ g_Mt + g_d (K=256, NOUT=128), grid (2,64)
template <int MODE>
__global__ __launch_bounds__(256) void gemm_tc(const float* __restrict__ Xext,
                                               float* __restrict__ Cext,
                                               const float* __restrict__ boext) {
    constexpr int K = (MODE == 0) ? KDd : Hh;
    constexpr int NOUT = (MODE == 0) ? Hh : VDd;
    const float* X = (MODE == 0) ? Xext : g_u;
    const float* W = (MODE == 0) ? g_AT : g_Mt;
    const float* bias = (MODE == 0) ? g_a0 : g_d;

    const int tid = threadIdx.x;
    const int warp = tid >> 5;
    const int lane = tid & 31;

    if (MODE == 0) {
        // fold g_u/g_denom zero-init into this kernel (256 blocks cover all)
        int bid = blockIdx.y * gridDim.x + blockIdx.x;  // 0..255
        float4 z = make_float4(0.f, 0.f, 0.f, 0.f);
        float4* u4 = (float4*)g_u;
        #pragma unroll
        for (int r = 0; r < 8; ++r) u4[(size_t)bid * 2048 + r * 256 + tid] = z;
        if (tid < 32) g_denom[bid * 32 + tid] = 0.0f;
    }

    __shared__ float Xs[128][20];   // raw fp32 X tile; stride 20 -> a0 reads hit 32 distinct banks
    __shared__ float Whi[16][68];   // tf32-rounded W tile
    __shared__ float Wlo[16][68];   // residual

    const int m0 = blockIdx.y * 128;
    const int n0 = blockIdx.x * 64;

    float acc[8][4] = {};   // 8 n-tiles (m16n8 each) x 4 regs

    for (int kc = 0; kc < K; kc += 16) {
        // cooperative X tile load: 128 rows x 16 k
        {
            int r = tid >> 1, c8 = (tid & 1) << 3;
            const float* src = X + (size_t)(m0 + r) * K + kc + c8;
            *(float4*)&Xs[r][c8]     = *(const float4*)src;
            *(float4*)&Xs[r][c8 + 4] = *(const float4*)(src + 4);
        }
        // cooperative W tile load + hi/lo split: 16 rows x 64 n
        {
            int wr = tid >> 4, wc = (tid & 15) << 2;
            float4 w = *(const float4*)(W + (size_t)(kc + wr) * NOUT + n0 + wc);
            float4 hi, lo;
            hi.x = __uint_as_float(f2tf32(w.x)); lo.x = w.x - hi.x;
            hi.y = __uint_as_float(f2tf32(w.y)); lo.y = w.y - hi.y;
            hi.z = __uint_as_float(f2tf32(w.z)); lo.z = w.z - hi.z;
            hi.w = __uint_as_float(f2tf32(w.w)); lo.w = w.w - hi.w;
            *(float4*)&Whi[wr][wc] = hi;
            *(float4*)&Wlo[wr][wc] = lo;
        }
        __syncthreads();

        #pragma unroll
        for (int ks = 0; ks < 16; ks += 8) {
            // A fragment (m16k8) for this warp's 16-row strip
            const int ar = (warp << 4) + (lane >> 2);
            const int ac = ks + (lane & 3);
            float af[4];
            af[0] = Xs[ar][ac];
            af[1] = Xs[ar + 8][ac];
            af[2] = Xs[ar][ac + 4];
            af[3] = Xs[ar + 8][ac + 4];
            uint32_t ah[4], al[4];
            #pragma unroll
            for (int i = 0; i < 4; ++i) {
                ah[i] = f2tf32(af[i]);
                al[i] = f2tf32(af[i] - __uint_as_float(ah[i]));
            }
            const int bk = ks + (lane & 3);
            const int bnb = lane >> 2;
            #pragma unroll
            for (int nt = 0; nt < 8; ++nt) {
                int bn = (nt << 3) + bnb;
                uint32_t bh0 = __float_as_uint(Whi[bk][bn]);
                uint32_t bh1 = __float_as_uint(Whi[bk + 4][bn]);
                uint32_t bl0 = __float_as_uint(Wlo[bk][bn]);
                uint32_t bl1 = __float_as_uint(Wlo[bk + 4][bn]);
                mma_tf32(acc[nt], ah, bh0, bh1);   // hi*hi
                mma_tf32(acc[nt], ah, bl0, bl1);   // hi*lo
                mma_tf32(acc[nt], al, bh0, bh1);   // lo*hi
            }
        }
        __syncthreads();
    }

    // epilogue: c0/c1 -> (r0, col..col+1), c2/c3 -> (r0+8, col..col+1)
    const int r0 = m0 + (warp << 4) + (lane >> 2);
    const int r1 = r0 + 8;
    const int cb = (lane & 3) << 1;

    if (MODE == 0) {
        #pragma unroll
        for (int nt = 0; nt < 8; ++nt) {
            int col = n0 + (nt << 3) + cb;
            float2 o0 = make_float2(acc[nt][0] + bias[col], acc[nt][1] + bias[col + 1]);
            float2 o1 = make_float2(acc[nt][2] + bias[col], acc[nt][3] + bias[col + 1]);
            *(float2*)(g_rs + (size_t)r0 * NOUT + col) = o0;
            *(float2*)(g_rs + (size_t)r1 * NOUT + col) = o1;
        }
    } else {
        float den0 = g_denom[r0];
        float den1 = g_denom[r1];
        float inv0 = (den0 > 0.0f) ? 1.0f / den0 : 0.0f;
        float inv1 = (den1 > 0.0f) ? 1.0f / den1 : 0.0f;
        #pragma unroll
        for (int nt = 0; nt < 8; ++nt) {
            int col = n0 + (nt << 3) + cb;
            float bx0 = bias[col], bx1 = bias[col + 1];
            float2 o0, o1;
            if (den0 > 0.0f) { o0 = make_float2(acc[nt][0] * inv0 + bx0, acc[nt][1] * inv0 + bx1); }
            else             { o0 = make_float2(boext[col], boext[col + 1]); }
            if (den1 > 0.0f) { o1 = make_float2(acc[nt][2] * inv1 + bx0, acc[nt][3] * inv1 + bx1); }
            else             { o1 = make_float2(boext[col], boext[col + 1]); }
            *(float2*)(Cext + (size_t)r0 * NOUT + col) = o0;
            *(float2*)(Cext + (size_t)r1 * NOUT + col) = o1;
        }
    }
}

// ---------------- fused main pass (unchanged from R5: at the HBM ceiling) -----
__device__ __forceinline__ void seg_flush(int b, int lane, float4 a0, float4 a1, float dacc) {
    float* up = g_u + (size_t)b * Hh;
    atomicAdd(up + lane * 4 + 0, a0.x);
    atomicAdd(up + lane * 4 + 1, a0.y);
    atomicAdd(up + lane * 4 + 2, a0.z);
    atomicAdd(up + lane * 4 + 3, a0.w);
    atomicAdd(up + 128 + lane * 4 + 0, a1.x);
    atomicAdd(up + 128 + lane * 4 + 1, a1.y);
    atomicAdd(up + 128 + lane * 4 + 2, a1.z);
    atomicAdd(up + 128 + lane * 4 + 3, a1.w);
    if (lane == 0) atomicAdd(&g_denom[b], dacc);
}

__device__ __forceinline__ float dot8(float4 k0, float4 k1, float4 r0, float4 r1) {
    return k0.x * r0.x + k0.y * r0.y + k0.z * r0.z + k0.w * r0.w
         + k1.x * r1.x + k1.y * r1.y + k1.z * r1.z + k1.w * r1.w;
}

__global__ __launch_bounds__(256, 3) void fused_attn(const float* __restrict__ key,
                                                     const float* __restrict__ value,
                                                     const int* __restrict__ batch) {
    const int wid = (blockIdx.x * blockDim.x + threadIdx.x) >> 5;
    const int lane = threadIdx.x & 31;
    const int n0 = wid * 64;
    if (n0 >= Nn) return;

    const float4* __restrict__ key4 = (const float4*)key;
    const float4* __restrict__ val4 = (const float4*)value;
    const float4* __restrict__ rs4 = (const float4*)g_rs;

    int cur = batch[n0] & (Bq - 1);
    float4 r0 = rs4[cur * 64 + lane];
    float4 r1 = rs4[cur * 64 + 32 + lane];

    float4 a0 = make_float4(0.f, 0.f, 0.f, 0.f);
    float4 a1 = make_float4(0.f, 0.f, 0.f, 0.f);
    float dacc = 0.0f;

    float4 ka0 = key4[(size_t)n0 * 64 + lane];
    float4 ka1 = key4[(size_t)n0 * 64 + 32 + lane];
    float4 kb0 = key4[(size_t)(n0 + 1) * 64 + lane];
    float4 kb1 = key4[(size_t)(n0 + 1) * 64 + 32 + lane];

    const int n_end = n0 + 64;
    for (int n = n0; n < n_end; n += 2) {
        int2 bb = *(const int2*)(batch + n);
        int b0 = bb.x & (Bq - 1);
        int b1 = bb.y & (Bq - 1);
        int np = n + 2 < Nn ? n + 2 : Nn - 2;

        if (b0 == cur && b1 == cur) {
            float pA = dot8(ka0, ka1, r0, r1);
            float pB = dot8(kb0, kb1, r0, r1);

            ka0 = key4[(size_t)np * 64 + lane];
            ka1 = key4[(size_t)np * 64 + 32 + lane];
            kb0 = key4[(size_t)(np + 1) * 64 + lane];
            kb1 = key4[(size_t)(np + 1) * 64 + 32 + lane];

            float4 va0 = val4[(size_t)n * 64 + lane];
            float4 va1 = val4[(size_t)n * 64 + 32 + lane];
            float4 vb0 = val4[(size_t)(n + 1) * 64 + lane];
            float4 vb1 = val4[(size_t)(n + 1) * 64 + 32 + lane];

            #pragma unroll
            for (int off = 16; off; off >>= 1) {
                pA += __shfl_xor_sync(0xffffffffu, pA, off);
                pB += __shfl_xor_sync(0xffffffffu, pB, off);
            }
            float eA = __expf(pA);
            float eB = __expf(pB);
            a0.x += eA * va0.x + eB * vb0.x; a0.y += eA * va0.y + eB * vb0.y;
            a0.z += eA * va0.z + eB * vb0.z; a0.w += eA * va0.w + eB * vb0.w;
            a1.x += eA * va1.x + eB * vb1.x; a1.y += eA * va1.y + eB * vb1.y;
            a1.z += eA * va1.z + eB * vb1.z; a1.w += eA * va1.w + eB * vb1.w;
            dacc += eA + eB;
        } else {
            float4 va0 = val4[(size_t)n * 64 + lane];
            float4 va1 = val4[(size_t)n * 64 + 32 + lane];
            float4 vb0 = val4[(size_t)(n + 1) * 64 + lane];
            float4 vb1 = val4[(size_t)(n + 1) * 64 + 32 + lane];

            if (b0 != cur) {
                seg_flush(cur, lane, a0, a1, dacc);
                a0 = make_float4(0.f, 0.f, 0.f, 0.f);
                a1 = make_float4(0.f, 0.f, 0.f, 0.f);
                dacc = 0.0f;
                cur = b0;
                r0 = rs4[cur * 64 + lane];
                r1 = rs4[cur * 64 + 32 + lane];
            }
            float pA = dot8(ka0, ka1, r0, r1);
            #pragma unroll
            for (int off = 16; off; off >>= 1) pA += __shfl_xor_sync(0xffffffffu, pA, off);
            float eA = __expf(pA);
            a0.x += eA * va0.x; a0.y += eA * va0.y; a0.z += eA * va0.z; a0.w += eA * va0.w;
            a1.x += eA * va1.x; a1.y += eA * va1.y; a1.z += eA * va1.z; a1.w += eA * va1.w;
            dacc += eA;

            if (b1 != cur) {
                seg_flush(cur, lane, a0, a1, dacc);
                a0 = make_float4(0.f, 0.f, 0.f, 0.f);
                a1 = make_float4(0.f, 0.f, 0.f, 0.f);
                dacc = 0.0f;
                cur = b1;
                r0 = rs4[cur * 64 + lane];
                r1 = rs4[cur * 64 + 32 + lane];
            }
            float pB = dot8(kb0, kb1, r0, r1);
            #pragma unroll
            for (int off = 16; off; off >>= 1) pB += __shfl_xor_sync(0xffffffffu, pB, off);
            float eB = __expf(pB);
            a0.x += eB * vb0.x; a0.y += eB * vb0.y; a0.z += eB * vb0.z; a0.w += eB * vb0.w;
            a1.x += eB * vb1.x; a1.y += eB * vb1.y; a1.z += eB * vb1.z; a1.w += eB * vb1.w;
            dacc += eB;

            ka0 = key4[(size_t)np * 64 + lane];
            ka1 = key4[(size_t)np * 64 + 32 + lane];
            kb0 = key4[(size_t)(np + 1) * 64 + lane];
            kb1 = key4[(size_t)(np + 1) * 64 + 32 + lane];
        }
    }
    seg_flush(cur, lane, a0, a1, dacc);
}

// ---------------- launch ------------------------------------------------------
extern "C" void kernel_launch(void* const* d_in, const int* in_sizes, int n_in,
                              void* d_out, int out_size) {
    const float* query = (const float*)d_in[0];
    const float* key = (const float*)d_in[1];
    const float* value = (const float*)d_in[2];
    const int* batch = (const int*)d_in[3];
    const float* Wq = (const float*)d_in[4];
    const float* bq = (const float*)d_in[5];
    const float* Wk = (const float*)d_in[6];
    const float* bk = (const float*)d_in[7];
    const float* Wv = (const float*)d_in[8];
    const float* bv = (const float*)d_in[9];
    const float* Wo = (const float*)d_in[10];
    const float* bo = (const float*)d_in[11];
    float* out = (float*)d_out;

    prep_all<<<KDd + 1 + Hh + 1, 256>>>(Wq, bq, Wk, bk, Wv, bv, Wo, bo);     // 386 blocks
    gemm_tc<0><<<dim3(Hh / 64, Bq / 128), 256>>>(query, nullptr, nullptr);   // (4,64)=256 blocks, zeroes g_u/g_denom
    fused_attn<<<Nn / 64 / 8, 256>>>(key, value, batch);
    gemm_tc<1><<<dim3(VDd / 64, Bq / 128), 256>>>(nullptr, out, bo);         // (2,64)=128 blocks
}

// round 7
// speedup vs baseline: 1.1472x; 1.0457x over previous
#include <cuda_runtime.h>
#include <cstdint>

#define Bq 8192
#define Nn 524288
#define Hh 256
#define KDd 128
#define VDd 128
#define SCALE 0.08838834764831845f  /* 1/sqrt(128) */

// ---------------- scratch (device globals; no allocation allowed) -----------
__device__ __align__(16) float g_rs[Bq * Hh];
__device__ __align__(16) float g_u[Bq * Hh];
__device__ __align__(16) float g_denom[Bq];
__device__ __align__(16) float g_AT[KDd * Hh];    // [128][256]
__device__ __align__(16) float g_a0[Hh];
__device__ __align__(16) float g_Mt[Hh * VDd];    // [256][128]
__device__ __align__(16) float g_d[VDd];

// ---------------- merged prep --------------------------------------------------
__global__ void prep_all(const float* __restrict__ Wq, const float* __restrict__ bq,
                         const float* __restrict__ Wk, const float* __restrict__ bk,
                         const float* __restrict__ Wv, const float* __restrict__ bv,
                         const float* __restrict__ Wo, const float* __restrict__ bo) {
    __shared__ float col[Hh];
    int blk = blockIdx.x;
    int t = threadIdx.x;  // 256 threads
    if (blk < KDd + 1) {
        int bi = blk;
        if (t < KDd) col[t] = (bi < KDd) ? Wq[t * KDd + bi] : bq[t];
        __syncthreads();
        float s = 0.0f;
        #pragma unroll 8
        for (int r = 0; r < KDd; ++r) s += Wk[r * Hh + t] * col[r];
        if (bi < KDd) g_AT[bi * Hh + t] = s * SCALE;
        else          g_a0[t] = s * SCALE;
    } else {
        int j = blk - (KDd + 1);   // 0..256
        if (t < VDd) col[t] = (j < Hh) ? Wv[t * Hh + j] : bv[t];
        __syncthreads();
        if (t < VDd) {
            float acc = 0.0f;
            const float4* wrow = (const float4*)(Wo + t * VDd);
            #pragma unroll 8
            for (int o4 = 0; o4 < VDd / 4; ++o4) {
                float4 w = wrow[o4];
                int o = o4 * 4;
                acc += w.x * col[o] + w.y * col[o + 1] + w.z * col[o + 2] + w.w * col[o + 3];
            }
            if (j < Hh) g_Mt[j * VDd + t] = acc;
            else        g_d[t] = acc + bo[t];
        }
    }
}

// ---------------- tf32 helpers -------------------------------------------------
__device__ __forceinline__ uint32_t f2tf32(float x) {
    uint32_t r;
    asm("cvt.rna.tf32.f32 %0, %1;" : "=r"(r) : "f"(x));
    return r;
}

__device__ __forceinline__ void mma_tf32(float* c, const uint32_t* a, uint32_t b0, uint32_t b1) {
    asm volatile(
        "mma.sync.aligned.m16n8k8.row.col.f32.tf32.tf32.f32 "
        "{%0,%1,%2,%3}, {%4,%5,%6,%7}, {%8,%9}, {%0,%1,%2,%3};"
        : "+f"(c[0]), "+f"(c[1]), "+f"(c[2]), "+f"(c[3])
        : "r"(a[0]), "r"(a[1]), "r"(a[2]), "r"(a[3]), "r"(b0), "r"(b1));
}

// ---------------- double-buffered 3xtf32 tensor-core GEMM ---------------------
// 256 threads (8 warps), N block tile = 64.
// MODE 0: g_rs = query @ g_AT + g_a0      K=128, NOUT=256, BM=128 -> grid (4,64)
//         warp tile m32 x n32 (mt=2, nt=4); warps_m=4, warps_n=2. + zero g_u.
// MODE 1: out = (g_u/den) @ g_Mt + g_d    K=256, NOUT=128, BM=64  -> grid (2,128)
//         warp tile m32 x n16 (mt=2, nt=2); warps_m=2, warps_n=4.
template <int MODE>
__global__ __launch_bounds__(256) void gemm_tc(const float* __restrict__ Xext,
                                               float* __restrict__ Cext,
                                               const float* __restrict__ boext) {
    constexpr int K = (MODE == 0) ? KDd : Hh;
    constexpr int NOUT = (MODE == 0) ? Hh : VDd;
    constexpr int BM = (MODE == 0) ? 128 : 64;
    constexpr int WARPS_M = (MODE == 0) ? 4 : 2;
    constexpr int NT = (MODE == 0) ? 4 : 2;       // n8 tiles per warp
    constexpr int NC = K / 16;                    // k-chunks
    const float* X = (MODE == 0) ? Xext : g_u;
    const float* W = (MODE == 0) ? g_AT : g_Mt;
    const float* bias = (MODE == 0) ? g_a0 : g_d;

    const int tid = threadIdx.x;
    const int warp = tid >> 5;
    const int lane = tid & 31;
    const int wm = warp % WARPS_M;      // m position (32-row strip)
    const int wn = warp / WARPS_M;      // n position (NT*8-col strip)

    if (MODE == 0) {
        // fold g_u/g_denom zero-init (256 blocks cover all of g_u)
        int bid = blockIdx.y * gridDim.x + blockIdx.x;  // 0..255
        float4 z = make_float4(0.f, 0.f, 0.f, 0.f);
        float4* u4 = (float4*)g_u;
        #pragma unroll
        for (int r = 0; r < 8; ++r) u4[(size_t)bid * 2048 + r * 256 + tid] = z;
        if (tid < 32) g_denom[bid * 32 + tid] = 0.0f;
    }

    __shared__ float Xs[2][BM][20];    // stride 20: A-frag reads conflict-free
    __shared__ float Whi[2][16][72];   // stride 72: B-frag reads conflict-free (8k+b)
    __shared__ float Wlo[2][16][72];

    const int m0 = blockIdx.y * BM;
    const int n0 = blockIdx.x * 64;

    // cooperative-load index precompute
    const int xr = (MODE == 0) ? (tid >> 1) : (tid >> 2);
    const int xc = (MODE == 0) ? ((tid & 1) << 3) : ((tid & 3) << 2);
    const int wr = tid >> 4;
    const int wc = (tid & 15) << 2;

    // ---- prologue: load chunk 0 straight to smem buffer 0
    {
        const float* xsrc = X + (size_t)(m0 + xr) * K + xc;
        *(float4*)&Xs[0][xr][xc] = *(const float4*)xsrc;
        if (MODE == 0) *(float4*)&Xs[0][xr][xc + 4] = *(const float4*)(xsrc + 4);
        float4 w = *(const float4*)(W + (size_t)wr * NOUT + n0 + wc);
        float4 hi, lo;
        hi.x = __uint_as_float(f2tf32(w.x)); lo.x = w.x - hi.x;
        hi.y = __uint_as_float(f2tf32(w.y)); lo.y = w.y - hi.y;
        hi.z = __uint_as_float(f2tf32(w.z)); lo.z = w.z - hi.z;
        hi.w = __uint_as_float(f2tf32(w.w)); lo.w = w.w - hi.w;
        *(float4*)&Whi[0][wr][wc] = hi;
        *(float4*)&Wlo[0][wr][wc] = lo;
    }
    __syncthreads();

    float acc[2][NT][4] = {};   // [mt][nt][regs]

    for (int c = 0; c < NC; ++c) {
        const int cb = c & 1;
        // ---- prefetch chunk c+1 into registers (no sync needed)
        float4 xpre0, xpre1, wpre;
        const bool more = (c + 1 < NC);
        if (more) {
            int kc = (c + 1) * 16;
            const float* xsrc = X + (size_t)(m0 + xr) * K + kc + xc;
            xpre0 = *(const float4*)xsrc;
            if (MODE == 0) xpre1 = *(const float4*)(xsrc + 4);
            wpre = *(const float4*)(W + (size_t)(kc + wr) * NOUT + n0 + wc);
        }

        // ---- compute on buffer cb
        #pragma unroll
        for (int ks = 0; ks < 16; ks += 8) {
            uint32_t ah[2][4], al[2][4];
            #pragma unroll
            for (int mt = 0; mt < 2; ++mt) {
                int ar = (wm << 5) + (mt << 4) + (lane >> 2);
                int ac = ks + (lane & 3);
                float a0 = Xs[cb][ar][ac];
                float a1 = Xs[cb][ar + 8][ac];
                float a2 = Xs[cb][ar][ac + 4];
                float a3 = Xs[cb][ar + 8][ac + 4];
                ah[mt][0] = f2tf32(a0); al[mt][0] = f2tf32(a0 - __uint_as_float(ah[mt][0]));
                ah[mt][1] = f2tf32(a1); al[mt][1] = f2tf32(a1 - __uint_as_float(ah[mt][1]));
                ah[mt][2] = f2tf32(a2); al[mt][2] = f2tf32(a2 - __uint_as_float(ah[mt][2]));
                ah[mt][3] = f2tf32(a3); al[mt][3] = f2tf32(a3 - __uint_as_float(ah[mt][3]));
            }
            const int bk = ks + (lane & 3);
            #pragma unroll
            for (int nt = 0; nt < NT; ++nt) {
                int bn = wn * (NT * 8) + (nt << 3) + (lane >> 2);
                uint32_t bh0 = __float_as_uint(Whi[cb][bk][bn]);
                uint32_t bh1 = __float_as_uint(Whi[cb][bk + 4][bn]);
                uint32_t bl0 = __float_as_uint(Wlo[cb][bk][bn]);
                uint32_t bl1 = __float_as_uint(Wlo[cb][bk + 4][bn]);
                #pragma unroll
                for (int mt = 0; mt < 2; ++mt) {
                    mma_tf32(acc[mt][nt], ah[mt], bh0, bh1);   // hi*hi
                    mma_tf32(acc[mt][nt], ah[mt], bl0, bl1);   // hi*lo
                    mma_tf32(acc[mt][nt], al[mt], bh0, bh1);   // lo*hi
                }
            }
        }

        // ---- stage prefetched regs into the other buffer
        if (more) {
            const int nb = cb ^ 1;
            *(float4*)&Xs[nb][xr][xc] = xpre0;
            if (MODE == 0) *(float4*)&Xs[nb][xr][xc + 4] = xpre1;
            float4 hi, lo;
            hi.x = __uint_as_float(f2tf32(wpre.x)); lo.x = wpre.x - hi.x;
            hi.y = __uint_as_float(f2tf32(wpre.y)); lo.y = wpre.y - hi.y;
            hi.z = __uint_as_float(f2tf32(wpre.z)); lo.z = wpre.z - hi.z;
            hi.w = __uint_as_float(f2tf32(wpre.w)); lo.w = wpre.w - hi.w;
            *(float4*)&Whi[nb][wr][wc] = hi;
            *(float4*)&Wlo[nb][wr][wc] = lo;
        }
        __syncthreads();
    }

    // ---- epilogue
    #pragma unroll
    for (int mt = 0; mt < 2; ++mt) {
        const int r0 = m0 + (wm << 5) + (mt << 4) + (lane >> 2);
        const int r1 = r0 + 8;
        const int cbase = n0 + wn * (NT * 8) + ((lane & 3) << 1);
        if (MODE == 0) {
            #pragma unroll
            for (int nt = 0; nt < NT; ++nt) {
                int col = cbase + (nt << 3);
                *(float2*)(g_rs + (size_t)r0 * NOUT + col) =
                    make_float2(acc[mt][nt][0] + bias[col], acc[mt][nt][1] + bias[col + 1]);
                *(float2*)(g_rs + (size_t)r1 * NOUT + col) =
                    make_float2(acc[mt][nt][2] + bias[col], acc[mt][nt][3] + bias[col + 1]);
            }
        } else {
            float den0 = g_denom[r0];
            float den1 = g_denom[r1];
            float inv0 = (den0 > 0.0f) ? 1.0f / den0 : 0.0f;
            float inv1 = (den1 > 0.0f) ? 1.0f / den1 : 0.0f;
            #pragma unroll
            for (int nt = 0; nt < NT; ++nt) {
                int col = cbase + (nt << 3);
                float bx0 = bias[col], bx1 = bias[col + 1];
                float2 o0, o1;
                if (den0 > 0.0f) o0 = make_float2(acc[mt][nt][0] * inv0 + bx0, acc[mt][nt][1] * inv0 + bx1);
                else             o0 = make_float2(boext[col], boext[col + 1]);
                if (den1 > 0.0f) o1 = make_float2(acc[mt][nt][2] * inv1 + bx0, acc[mt][nt][3] * inv1 + bx1);
                else             o1 = make_float2(boext[col], boext[col + 1]);
                *(float2*)(Cext + (size_t)r0 * NOUT + col) = o0;
                *(float2*)(Cext + (size_t)r1 * NOUT + col) = o1;
            }
        }
    }
}

// ---------------- fused main pass (frozen: at the HBM ceiling) -----------------
__device__ __forceinline__ void seg_flush(int b, int lane, float4 a0, float4 a1, float dacc) {
    float* up = g_u + (size_t)b * Hh;
    atomicAdd(up + lane * 4 + 0, a0.x);
    atomicAdd(up + lane * 4 + 1, a0.y);
    atomicAdd(up + lane * 4 + 2, a0.z);
    atomicAdd(up + lane * 4 + 3, a0.w);
    atomicAdd(up + 128 + lane * 4 + 0, a1.x);
    atomicAdd(up + 128 + lane * 4 + 1, a1.y);
    atomicAdd(up + 128 + lane * 4 + 2, a1.z);
    atomicAdd(up + 128 + lane * 4 + 3, a1.w);
    if (lane == 0) atomicAdd(&g_denom[b], dacc);
}

__device__ __forceinline__ float dot8(float4 k0, float4 k1, float4 r0, float4 r1) {
    return k0.x * r0.x + k0.y * r0.y + k0.z * r0.z + k0.w * r0.w
         + k1.x * r1.x + k1.y * r1.y + k1.z * r1.z + k1.w * r1.w;
}

__global__ __launch_bounds__(256, 3) void fused_attn(const float* __restrict__ key,
                                                     const float* __restrict__ value,
                                                     const int* __restrict__ batch) {
    const int wid = (blockIdx.x * blockDim.x + threadIdx.x) >> 5;
    const int lane = threadIdx.x & 31;
    const int n0 = wid * 64;
    if (n0 >= Nn) return;

    const float4* __restrict__ key4 = (const float4*)key;
    const float4* __restrict__ val4 = (const float4*)value;
    const float4* __restrict__ rs4 = (const float4*)g_rs;

    int cur = batch[n0] & (Bq - 1);
    float4 r0 = rs4[cur * 64 + lane];
    float4 r1 = rs4[cur * 64 + 32 + lane];

    float4 a0 = make_float4(0.f, 0.f, 0.f, 0.f);
    float4 a1 = make_float4(0.f, 0.f, 0.f, 0.f);
    float dacc = 0.0f;

    float4 ka0 = key4[(size_t)n0 * 64 + lane];
    float4 ka1 = key4[(size_t)n0 * 64 + 32 + lane];
    float4 kb0 = key4[(size_t)(n0 + 1) * 64 + lane];
    float4 kb1 = key4[(size_t)(n0 + 1) * 64 + 32 + lane];

    const int n_end = n0 + 64;
    for (int n = n0; n < n_end; n += 2) {
        int2 bb = *(const int2*)(batch + n);
        int b0 = bb.x & (Bq - 1);
        int b1 = bb.y & (Bq - 1);
        int np = n + 2 < Nn ? n + 2 : Nn - 2;

        if (b0 == cur && b1 == cur) {
            float pA = dot8(ka0, ka1, r0, r1);
            float pB = dot8(kb0, kb1, r0, r1);

            ka0 = key4[(size_t)np * 64 + lane];
            ka1 = key4[(size_t)np * 64 + 32 + lane];
            kb0 = key4[(size_t)(np + 1) * 64 + lane];
            kb1 = key4[(size_t)(np + 1) * 64 + 32 + lane];

            float4 va0 = val4[(size_t)n * 64 + lane];
            float4 va1 = val4[(size_t)n * 64 + 32 + lane];
            float4 vb0 = val4[(size_t)(n + 1) * 64 + lane];
            float4 vb1 = val4[(size_t)(n + 1) * 64 + 32 + lane];

            #pragma unroll
            for (int off = 16; off; off >>= 1) {
                pA += __shfl_xor_sync(0xffffffffu, pA, off);
                pB += __shfl_xor_sync(0xffffffffu, pB, off);
            }
            float eA = __expf(pA);
            float eB = __expf(pB);
            a0.x += eA * va0.x + eB * vb0.x; a0.y += eA * va0.y + eB * vb0.y;
            a0.z += eA * va0.z + eB * vb0.z; a0.w += eA * va0.w + eB * vb0.w;
            a1.x += eA * va1.x + eB * vb1.x; a1.y += eA * va1.y + eB * vb1.y;
            a1.z += eA * va1.z + eB * vb1.z; a1.w += eA * va1.w + eB * vb1.w;
            dacc += eA + eB;
        } else {
            float4 va0 = val4[(size_t)n * 64 + lane];
            float4 va1 = val4[(size_t)n * 64 + 32 + lane];
            float4 vb0 = val4[(size_t)(n + 1) * 64 + lane];
            float4 vb1 = val4[(size_t)(n + 1) * 64 + 32 + lane];

            if (b0 != cur) {
                seg_flush(cur, lane, a0, a1, dacc);
                a0 = make_float4(0.f, 0.f, 0.f, 0.f);
                a1 = make_float4(0.f, 0.f, 0.f, 0.f);
                dacc = 0.0f;
                cur = b0;
                r0 = rs4[cur * 64 + lane];
                r1 = rs4[cur * 64 + 32 + lane];
            }
            float pA = dot8(ka0, ka1, r0, r1);
            #pragma unroll
            for (int off = 16; off; off >>= 1) pA += __shfl_xor_sync(0xffffffffu, pA, off);
            float eA = __expf(pA);
            a0.x += eA * va0.x; a0.y += eA * va0.y; a0.z += eA * va0.z; a0.w += eA * va0.w;
            a1.x += eA * va1.x; a1.y += eA * va1.y; a1.z += eA * va1.z; a1.w += eA * va1.w;
            dacc += eA;

            if (b1 != cur) {
                seg_flush(cur, lane, a0, a1, dacc);
                a0 = make_float4(0.f, 0.f, 0.f, 0.f);
                a1 = make_float4(0.f, 0.f, 0.f, 0.f);
                dacc = 0.0f;
                cur = b1;
                r0 = rs4[cur * 64 + lane];
                r1 = rs4[cur * 64 + 32 + lane];
            }
            float pB = dot8(kb0, kb1, r0, r1);
            #pragma unroll
            for (int off = 16; off; off >>= 1) pB += __shfl_xor_sync(0xffffffffu, pB, off);
            float eB = __expf(pB);
            a0.x += eB * vb0.x; a0.y += eB * vb0.y; a0.z += eB * vb0.z; a0.w += eB * vb0.w;
            a1.x += eB * vb1.x; a1.y += eB * vb1.y; a1.z += eB * vb1.z; a1.w += eB * vb1.w;
            dacc += eB;

            ka0 = key4[(size_t)np * 64 + lane];
            ka1 = key4[(size_t)np * 64 + 32 + lane];
            kb0 = key4[(size_t)(np + 1) * 64 + lane];
            kb1 = key4[(size_t)(np + 1) * 64 + 32 + lane];
        }
    }
    seg_flush(cur, lane, a0, a1, dacc);
}

// ---------------- launch ------------------------------------------------------
extern "C" void kernel_launch(void* const* d_in, const int* in_sizes, int n_in,
                              void* d_out, int out_size) {
    const float* query = (const float*)d_in[0];
    const float* key = (const float*)d_in[1];
    const float* value = (const float*)d_in[2];
    const int* batch = (const int*)d_in[3];
    const float* Wq = (const float*)d_in[4];
    const float* bq = (const float*)d_in[5];
    const float* Wk = (const float*)d_in[6];
    const float* bk = (const float*)d_in[7];
    const float* Wv = (const float*)d_in[8];
    const float* bv = (const float*)d_in[9];
    const float* Wo = (const float*)d_in[10];
    const float* bo = (const float*)d_in[11];
    float* out = (float*)d_out;

    prep_all<<<KDd + 1 + Hh + 1, 256>>>(Wq, bq, Wk, bk, Wv, bv, Wo, bo);     // 386 blocks
    gemm_tc<0><<<dim3(Hh / 64, Bq / 128), 256>>>(query, nullptr, nullptr);   // (4,64)=256 blocks
    fused_attn<<<Nn / 64 / 8, 256>>>(key, value, batch);
    gemm_tc<1><<<dim3(VDd / 64, Bq / 64), 256>>>(nullptr, out, bo);          // (2,128)=256 blocks
}